// round 13
// baseline (speedup 1.0000x reference)
#include <cuda_runtime.h>
#include <cuda_fp16.h>
#include <math.h>
#include <stdint.h>

#define NDEST 8192
#define NSRC  8192
#define FEATD 1024
#define TFD   256
#define EMB   64
#define HID   128
#define HEADS 2
#define SCAP  1024

// scratch (static device arrays: allocation-free)
__device__ __half g_fcW_h[TFD * FEATD];                  // 0.5 MB
__device__ __half g_decW_h[FEATD * TFD];                 // 0.5 MB
__device__ __half g_trans_h[(size_t)NSRC * TFD];         // 4 MB
__device__ __half g_hsrc_h[(size_t)NSRC * 2 * HID];      // 4 MB, [n][head][128]
__device__ float  g_q[(size_t)NDEST * 2 * HID];          // 8 MB, [m][head][128]
__device__ float  g_wc[HEADS * EMB * HID];               // 64 KB
__device__ float  g_w[(size_t)NDEST * SCAP];             // 32 MB CSR weights
__device__ unsigned short g_idx[(size_t)NDEST * SCAP];   // 16 MB CSR indices
__device__ int    g_cnt[NDEST];                          // 32 KB

// ---------------------------------------------------------------------------
// f32 -> f16 conversion (n multiple of 4) — weights only (small)
// ---------------------------------------------------------------------------
__global__ void f2h_kernel(const float* __restrict__ src,
                           __half* __restrict__ dst, int n)
{
  int i = (blockIdx.x * blockDim.x + threadIdx.x) * 4;
  if (i < n) {
    float4 v = *(const float4*)(src + i);
    *(__half2*)(dst + i)     = __floats2half2_rn(v.x, v.y);
    *(__half2*)(dst + i + 2) = __floats2half2_rn(v.z, v.w);
  }
}

__device__ __forceinline__ uint32_t h2u(__half2 h) {
  return *(uint32_t*)&h;
}

// fast exp(elu(s)) — __expf is MUFU.EX2-based, rel err ~1e-6
__device__ __forceinline__ float exp_elu(float s) {
  return __expf(s > 0.f ? s : __expf(s) - 1.f);
}

// ===========================================================================
// FP16 tensor-core GEMM:  C[M,N] = A[M,K] @ B[N,K]^T (+ bias[N])
// mma.m16n8k16.f16, fp32 accum. BM=128, BN=64, BK=32, 256 threads, 8 warps.
// Double-buffered smem; pair-permuted layout (LDS.64 fragments, stride 40).
// A_FLOAT: A fp32 in gmem, converted to fp16 during the smem store.
// ===========================================================================
__device__ __forceinline__ void mma_f16(float* d, const uint32_t* a, uint2 b) {
  asm volatile(
      "mma.sync.aligned.m16n8k16.row.col.f32.f16.f16.f32 "
      "{%0,%1,%2,%3}, {%4,%5,%6,%7}, {%8,%9}, {%0,%1,%2,%3};\n"
      : "+f"(d[0]), "+f"(d[1]), "+f"(d[2]), "+f"(d[3])
      : "r"(a[0]), "r"(a[1]), "r"(a[2]), "r"(a[3]), "r"(b.x), "r"(b.y));
}

#define GSM_BYTES ((2 * 128 * 40 + 2 * 64 * 40) * 4)

template<bool A_FLOAT, bool HALF_OUT>
__global__ __launch_bounds__(256, 2) void h16gemm_k(
    const void* __restrict__ Av, const __half* __restrict__ B,
    const float* __restrict__ bias, void* __restrict__ Cv,
    int M, int N, int K)
{
  extern __shared__ uint32_t smdyn[];
  uint32_t (*Asm)[40] = (uint32_t(*)[40])smdyn;                  // 2 x 128
  uint32_t (*Bsm)[40] = (uint32_t(*)[40])(smdyn + 2 * 128 * 40); // 2 x 64

  const int t = threadIdx.x;
  const int lane = t & 31, w = t >> 5;
  const int wm = (w & 3) * 32, wn = (w >> 2) * 32;
  const int g = lane >> 2, c = lane & 3;
  const int row0 = blockIdx.y * 128, col0 = blockIdx.x * 64;

  const int arow = t >> 1, as = t & 1;
  const int brow = t >> 2, bq = t & 3, bs = bq >> 1, bl = bq & 1;

  const float*  pAf = (const float*)Av  + (size_t)(row0 + arow) * K + as * 16;
  const __half* pAh = (const __half*)Av + (size_t)(row0 + arow) * K + as * 16;
  const __half* pB  = B + (size_t)(col0 + brow) * K + bs * 16 + bl * 8;

  float4 fa0, fa1, fa2, fa3;
  uint4  qa0, qa1;
  uint4  qb;

  if (A_FLOAT) {
    fa0 = *(const float4*)(pAf);
    fa1 = *(const float4*)(pAf + 4);
    fa2 = *(const float4*)(pAf + 8);
    fa3 = *(const float4*)(pAf + 12);
  } else {
    qa0 = *(const uint4*)(pAh);
    qa1 = *(const uint4*)(pAh + 8);
  }
  qb = *(const uint4*)(pB);

  auto storeA = [&](uint32_t (*An)[40]) {
    uint32_t* d = &An[arow][as * 8];
    if (A_FLOAT) {
      d[0] = h2u(__floats2half2_rn(fa0.x, fa0.y));
      d[2] = h2u(__floats2half2_rn(fa0.z, fa0.w));
      d[4] = h2u(__floats2half2_rn(fa1.x, fa1.y));
      d[6] = h2u(__floats2half2_rn(fa1.z, fa1.w));
      d[1] = h2u(__floats2half2_rn(fa2.x, fa2.y));
      d[3] = h2u(__floats2half2_rn(fa2.z, fa2.w));
      d[5] = h2u(__floats2half2_rn(fa3.x, fa3.y));
      d[7] = h2u(__floats2half2_rn(fa3.z, fa3.w));
    } else {
      d[0]=qa0.x; d[2]=qa0.y; d[4]=qa0.z; d[6]=qa0.w;
      d[1]=qa1.x; d[3]=qa1.y; d[5]=qa1.z; d[7]=qa1.w;
    }
  };
  auto storeB = [&](uint32_t (*Bn)[40]) {
    uint32_t* e = &Bn[brow][bs * 8 + bl];
    e[0]=qb.x; e[2]=qb.y; e[4]=qb.z; e[6]=qb.w;
  };

  storeA(Asm);
  storeB(Bsm);
  __syncthreads();

  float acc[2][4][4] = {};
  int s = 0;

  for (int k0 = 0; k0 < K; k0 += 32) {
    const bool nxt = (k0 + 32 < K);
    if (nxt) {
      if (A_FLOAT) {
        fa0 = *(const float4*)(pAf + k0 + 32);
        fa1 = *(const float4*)(pAf + k0 + 36);
        fa2 = *(const float4*)(pAf + k0 + 40);
        fa3 = *(const float4*)(pAf + k0 + 44);
      } else {
        qa0 = *(const uint4*)(pAh + k0 + 32);
        qa1 = *(const uint4*)(pAh + k0 + 40);
      }
      qb = *(const uint4*)(pB + k0 + 32);
    }
    const uint32_t (*Ac)[40] = Asm + s * 128;
    const uint32_t (*Bc)[40] = Bsm + s * 64;

    #pragma unroll
    for (int ks = 0; ks < 2; ks++) {
      uint32_t af[2][4];
      uint2 bf[4];
      #pragma unroll
      for (int mi = 0; mi < 2; mi++) {
        uint2 lo = *(const uint2*)&Ac[wm + mi * 16 + g][ks * 8 + 2 * c];
        uint2 hi = *(const uint2*)&Ac[wm + mi * 16 + g + 8][ks * 8 + 2 * c];
        af[mi][0] = lo.x; af[mi][1] = hi.x; af[mi][2] = lo.y; af[mi][3] = hi.y;
      }
      #pragma unroll
      for (int ni = 0; ni < 4; ni++)
        bf[ni] = *(const uint2*)&Bc[wn + ni * 8 + g][ks * 8 + 2 * c];
      #pragma unroll
      for (int mi = 0; mi < 2; mi++)
        #pragma unroll
        for (int ni = 0; ni < 4; ni++)
          mma_f16(acc[mi][ni], af[mi], bf[ni]);
    }

    if (nxt) {
      storeA(Asm + (s ^ 1) * 128);
      storeB(Bsm + (s ^ 1) * 64);
      __syncthreads();
      s ^= 1;
    }
  }

  #pragma unroll
  for (int mi = 0; mi < 2; mi++) {
    int r = row0 + wm + mi * 16 + g;
    #pragma unroll
    for (int ni = 0; ni < 4; ni++) {
      int cc = col0 + wn + ni * 8 + 2 * c;
      float2 bv = *(const float2*)(bias + cc);
      float* d = acc[mi][ni];
      if (HALF_OUT) {
        __half* Ch = (__half*)Cv;
        *(__half2*)(Ch + (size_t)r * N + cc) =
            __floats2half2_rn(d[0] + bv.x, d[1] + bv.y);
        *(__half2*)(Ch + (size_t)(r + 8) * N + cc) =
            __floats2half2_rn(d[2] + bv.x, d[3] + bv.y);
      } else {
        float* Cf = (float*)Cv;
        *(float2*)(Cf + (size_t)r * N + cc) =
            make_float2(d[0] + bv.x, d[1] + bv.y);
        *(float2*)(Cf + (size_t)(r + 8) * N + cc) =
            make_float2(d[2] + bv.x, d[3] + bv.y);
      }
    }
  }
}

// ---------------------------------------------------------------------------
// Merged fp32 SGEMM for BOTH score-path projections in one launch.
// z = 0,1: hsrc_h[n][head][128] (fp16)  = emb_src  @ att_W[head]
// z = 2,3: q[m][head][128]      (fp32)  = emb_dest @ wc[head]
// ---------------------------------------------------------------------------
__global__ __launch_bounds__(256) void sgemm4_k(
    const float* __restrict__ emb_src, const float* __restrict__ emb_dest,
    const float* __restrict__ attW, const float* __restrict__ wc,
    __half* __restrict__ hsrc_h, float* __restrict__ q)
{
  const int z = blockIdx.z;
  const int head = z & 1, sel = z >> 1;
  const int N = HID, K = EMB;
  const float* A  = sel ? emb_dest : emb_src;
  const float* Bp = (sel ? wc : attW) + head * EMB * HID;

  __shared__ float As[16][68];
  __shared__ float Bs[16][68];

  const int t  = threadIdx.x;
  const int tx = t & 15;
  const int ty = t >> 4;
  const int row0 = blockIdx.y << 6;
  const int col0 = blockIdx.x << 6;

  const int aRow = t >> 2;
  const int aK   = (t & 3) << 2;
  const int bK   = t >> 4;
  const int bN   = (t & 15) << 2;

  float acc[4][4] = {};

  for (int k0 = 0; k0 < K; k0 += 16) {
    float4 a4 = *(const float4*)(A + (size_t)(row0 + aRow) * K + (k0 + aK));
    As[aK+0][aRow] = a4.x; As[aK+1][aRow] = a4.y;
    As[aK+2][aRow] = a4.z; As[aK+3][aRow] = a4.w;
    float4 b4 = *(const float4*)(Bp + (size_t)(k0 + bK) * N + (col0 + bN));
    *(float4*)&Bs[bK][bN] = b4;
    __syncthreads();
    #pragma unroll
    for (int k = 0; k < 16; k++) {
      float4 a = *(const float4*)&As[k][ty << 2];
      float4 b = *(const float4*)&Bs[k][tx << 2];
      acc[0][0] += a.x*b.x; acc[0][1] += a.x*b.y; acc[0][2] += a.x*b.z; acc[0][3] += a.x*b.w;
      acc[1][0] += a.y*b.x; acc[1][1] += a.y*b.y; acc[1][2] += a.y*b.z; acc[1][3] += a.y*b.w;
      acc[2][0] += a.z*b.x; acc[2][1] += a.z*b.y; acc[2][2] += a.z*b.z; acc[2][3] += a.z*b.w;
      acc[3][0] += a.w*b.x; acc[3][1] += a.w*b.y; acc[3][2] += a.w*b.z; acc[3][3] += a.w*b.w;
    }
    __syncthreads();
  }

  #pragma unroll
  for (int i = 0; i < 4; i++) {
    int row = row0 + (ty << 2) + i;
    int cc  = col0 + (tx << 2);
    if (sel) {
      *(float4*)(q + (((size_t)row * 2 + head) << 7) + cc) =
          make_float4(acc[i][0], acc[i][1], acc[i][2], acc[i][3]);
    } else {
      uint2 hv = make_uint2(
          h2u(__floats2half2_rn(acc[i][0], acc[i][1])),
          h2u(__floats2half2_rn(acc[i][2], acc[i][3])));
      *(uint2*)(hsrc_h + (((size_t)row * 2 + head) << 7) + cc) = hv;
    }
  }
}

// ---------------------------------------------------------------------------
// Wc[h] = att_W[h] (64x128) @ att_W2[h] (128x128)
// ---------------------------------------------------------------------------
__global__ __launch_bounds__(128) void wc_kernel(
    const float* __restrict__ attW, const float* __restrict__ attW2,
    float* __restrict__ wc)
{
  const int b = blockIdx.x;              // 0..127
  const int h = b >> 6, e = b & 63;
  const int d = threadIdx.x;             // 0..127
  __shared__ float Wsh[HID];
  Wsh[d] = attW[h * EMB * HID + e * HID + d];
  __syncthreads();
  const float* W2 = attW2 + h * HID * HID;
  float s = 0.f;
  #pragma unroll 16
  for (int k = 0; k < HID; k++) s += Wsh[k] * W2[k * HID + d];
  wc[h * EMB * HID + e * HID + d] = s;
}

// ---------------------------------------------------------------------------
// per-THREAD score: stream one hsrc row (32 LDG.128), dot against broadcast
// smem q, exp. No shuffles; all nnz scores compute in one parallel round.
// ---------------------------------------------------------------------------
__device__ __forceinline__ float2 score_exp_thread(
    int n, const float* qsh, const __half* __restrict__ hsrc_h)
{
  const uint4* kr = (const uint4*)(hsrc_h + ((size_t)n << 8));  // 32 x 16B
  const float4* q4 = (const float4*)qsh;
  float s0 = 0.f, s1 = 0.f;
  #pragma unroll 8
  for (int k = 0; k < 16; k++) {
    uint4 u = kr[k];        // head0 halves 8k..8k+7
    uint4 v = kr[16 + k];   // head1
    float4 qa = q4[2*k], qb = q4[2*k + 1];
    float4 qc = q4[32 + 2*k], qd = q4[32 + 2*k + 1];
    float2 h0 = __half22float2(*(__half2*)&u.x);
    float2 h1 = __half22float2(*(__half2*)&u.y);
    float2 h2 = __half22float2(*(__half2*)&u.z);
    float2 h3 = __half22float2(*(__half2*)&u.w);
    s0 += qa.x*h0.x + qa.y*h0.y + qa.z*h1.x + qa.w*h1.y
        + qb.x*h2.x + qb.y*h2.y + qb.z*h3.x + qb.w*h3.y;
    float2 g0 = __half22float2(*(__half2*)&v.x);
    float2 g1 = __half22float2(*(__half2*)&v.y);
    float2 g2 = __half22float2(*(__half2*)&v.z);
    float2 g3 = __half22float2(*(__half2*)&v.w);
    s1 += qc.x*g0.x + qc.y*g0.y + qc.z*g1.x + qc.w*g1.y
        + qd.x*g2.x + qd.y*g2.y + qd.z*g3.x + qd.w*g3.y;
  }
  return make_float2(exp_elu(s0), exp_elu(s1));
}

// warp-collective variant (fallback paths only)
__device__ __forceinline__ float2 score_exp_pair(
    int n, const float* qsh, const __half* __restrict__ hsrc_h, int lane)
{
  const uint2* kk = (const uint2*)(hsrc_h + ((size_t)n << 8));
  uint2 u0 = kk[lane];
  uint2 u1 = kk[32 + lane];
  const float4 a0 = ((const float4*)qsh)[lane];
  const float4 a1 = ((const float4*)qsh)[32 + lane];
  float2 p00 = __half22float2(*(__half2*)&u0.x);
  float2 p01 = __half22float2(*(__half2*)&u0.y);
  float2 p10 = __half22float2(*(__half2*)&u1.x);
  float2 p11 = __half22float2(*(__half2*)&u1.y);
  float s0 = a0.x*p00.x + a0.y*p00.y + a0.z*p01.x + a0.w*p01.y;
  float s1 = a1.x*p10.x + a1.y*p10.y + a1.z*p11.x + a1.w*p11.y;
  #pragma unroll
  for (int o = 16; o; o >>= 1) {
    s0 += __shfl_xor_sync(0xffffffffu, s0, o);
    s1 += __shfl_xor_sync(0xffffffffu, s1, o);
  }
  return make_float2(exp_elu(s0), exp_elu(s1));
}

// ---------------------------------------------------------------------------
// Kernel 1: per dest row m — bias scan, compact, thread-per-score, normalize.
// Writes CSR: w[m][j] = e0/(2*Z0) + e1/(2*Z1), idx[m][j], cnt[m].
// ---------------------------------------------------------------------------
__global__ __launch_bounds__(256) void score_kernel(
    const float* __restrict__ bias,
    const float* __restrict__ q,            // [NDEST][2][128] fp32
    const __half* __restrict__ hsrc,        // [NSRC][2][128] fp16
    float* __restrict__ wout,               // [NDEST][SCAP]
    unsigned short* __restrict__ idxout,    // [NDEST][SCAP]
    int* __restrict__ cntout)
{
  const int m = blockIdx.x;
  const int t = threadIdx.x;
  const int warp = t >> 5, lane = t & 31;

  __shared__ unsigned short sidx[SCAP];        // 2 KB
  __shared__ __align__(16) float qsh[2 * HID]; // 1 KB
  __shared__ float2 ecache[SCAP];              // 8 KB
  __shared__ int s_warp[8];
  __shared__ float sZ0, sZ1;

  qsh[t] = q[((size_t)m << 8) + t];

  const float4* brow4 = (const float4*)(bias + (size_t)m * NSRC);

  float4 v[8];
  int cnt = 0;
  #pragma unroll
  for (int i = 0; i < 8; i++) {
    v[i] = brow4[t * 8 + i];
    cnt += (v[i].x>0.f)+(v[i].y>0.f)+(v[i].z>0.f)+(v[i].w>0.f);
  }
  int inc = cnt;
  #pragma unroll
  for (int o = 1; o < 32; o <<= 1) {
    int u = __shfl_up_sync(0xffffffffu, inc, o);
    if (lane >= o) inc += u;
  }
  if (lane == 31) s_warp[warp] = inc;
  __syncthreads();
  int nnz = 0, woff = 0;
  #pragma unroll
  for (int i = 0; i < 8; i++) {
    int u = s_warp[i];
    nnz += u;
    if (i < warp) woff += u;
  }

  if (nnz == 0 || nnz > SCAP) {
    if (t == 0) cntout[m] = nnz;   // gather_kernel fallback handles it
    return;
  }

  int base = woff + inc - cnt;
  #pragma unroll
  for (int i = 0; i < 8; i++) {
    int b0 = t * 32 + i * 4;
    if (v[i].x > 0.f) sidx[base++] = (unsigned short)(b0 + 0);
    if (v[i].y > 0.f) sidx[base++] = (unsigned short)(b0 + 1);
    if (v[i].z > 0.f) sidx[base++] = (unsigned short)(b0 + 2);
    if (v[i].w > 0.f) sidx[base++] = (unsigned short)(b0 + 3);
  }
  __syncthreads();

  // thread-per-score: one parallel round for nnz <= 256 (typical 82)
  for (int j = t; j < nnz; j += 256)
    ecache[j] = score_exp_thread(sidx[j], qsh, hsrc);
  __syncthreads();

  // warp 0 reduces Z
  if (warp == 0) {
    float z0 = 0.f, z1 = 0.f;
    for (int j = lane; j < nnz; j += 32) {
      float2 e = ecache[j];
      z0 += e.x; z1 += e.y;
    }
    #pragma unroll
    for (int o = 16; o; o >>= 1) {
      z0 += __shfl_xor_sync(0xffffffffu, z0, o);
      z1 += __shfl_xor_sync(0xffffffffu, z1, o);
    }
    if (lane == 0) { sZ0 = z0; sZ1 = z1; }
  }
  __syncthreads();
  const float inv0 = 0.5f / sZ0;
  const float inv1 = 0.5f / sZ1;

  float* wrow = wout + (size_t)m * SCAP;
  unsigned short* irow = idxout + (size_t)m * SCAP;
  for (int j = t; j < nnz; j += 256) {
    float2 e = ecache[j];
    wrow[j] = e.x * inv0 + e.y * inv1;
    irow[j] = sidx[j];
  }
  if (t == 0) cntout[m] = nnz;
}

// ---------------------------------------------------------------------------
// Kernel 2: per dest row m — pure CSR gather. 128 threads, one half2 column
// pair each, 8-deep MLP. Fallbacks (cnt==0 uniform; cnt>SCAP exact two-pass
// recompute) keep correctness for impossible cases.
// ---------------------------------------------------------------------------
__global__ __launch_bounds__(128) void gather_kernel(
    const float* __restrict__ w,            // [NDEST][SCAP]
    const unsigned short* __restrict__ idx, // [NDEST][SCAP]
    const int* __restrict__ cnt,
    const __half* __restrict__ xh,          // [NSRC][TFD] fp16
    const float* __restrict__ bias,
    const float* __restrict__ q,
    const __half* __restrict__ hsrc,
    float* __restrict__ out)                // [NDEST][TFD]
{
  const int m = blockIdx.x;
  const int t = threadIdx.x;                // 0..127; cols 2t, 2t+1
  const int n = cnt[m];

  __shared__ float wsh[SCAP];               // 4 KB
  __shared__ unsigned short ish[SCAP];      // 2 KB

  if (n > 0 && n <= SCAP) {
    const float* wrow = w + (size_t)m * SCAP;
    const unsigned short* irow = idx + (size_t)m * SCAP;
    for (int j = t; j < n; j += 128) {
      wsh[j] = wrow[j];
      ish[j] = irow[j];
    }
    __syncthreads();

    float ax = 0.f, ay = 0.f;
    int j = 0;
    for (; j + 8 <= n; j += 8) {
      int r0 = ish[j+0] * TFD, r1 = ish[j+1] * TFD;
      int r2 = ish[j+2] * TFD, r3 = ish[j+3] * TFD;
      int r4 = ish[j+4] * TFD, r5 = ish[j+5] * TFD;
      int r6 = ish[j+6] * TFD, r7 = ish[j+7] * TFD;
      float2 x0 = __half22float2(*(const __half2*)(xh + r0 + 2*t));
      float2 x1 = __half22float2(*(const __half2*)(xh + r1 + 2*t));
      float2 x2 = __half22float2(*(const __half2*)(xh + r2 + 2*t));
      float2 x3 = __half22float2(*(const __half2*)(xh + r3 + 2*t));
      float2 x4 = __half22float2(*(const __half2*)(xh + r4 + 2*t));
      float2 x5 = __half22float2(*(const __half2*)(xh + r5 + 2*t));
      float2 x6 = __half22float2(*(const __half2*)(xh + r6 + 2*t));
      float2 x7 = __half22float2(*(const __half2*)(xh + r7 + 2*t));
      float w0 = wsh[j+0], w1 = wsh[j+1], w2 = wsh[j+2], w3 = wsh[j+3];
      float w4 = wsh[j+4], w5 = wsh[j+5], w6 = wsh[j+6], w7 = wsh[j+7];
      ax += w0*x0.x + w1*x1.x + w2*x2.x + w3*x3.x
          + w4*x4.x + w5*x5.x + w6*x6.x + w7*x7.x;
      ay += w0*x0.y + w1*x1.y + w2*x2.y + w3*x3.y
          + w4*x4.y + w5*x5.y + w6*x6.y + w7*x7.y;
    }
    for (; j < n; j++) {
      float2 x = __half22float2(*(const __half2*)(xh + ish[j] * TFD + 2*t));
      float wv = wsh[j];
      ax += wv * x.x; ay += wv * x.y;
    }
    *(float2*)(out + (size_t)m * TFD + 2*t) = make_float2(ax, ay);
    return;
  }

  if (n == 0) {
    // all masked: softmax uniform over all sources (reference behavior)
    float ax = 0.f, ay = 0.f;
    for (int r = 0; r < NSRC; r++) {
      float2 x = __half22float2(*(const __half2*)(xh + (size_t)r * TFD + 2*t));
      ax += x.x; ay += x.y;
    }
    *(float2*)(out + (size_t)m * TFD + 2*t) =
        make_float2(ax * (1.0f / NSRC), ay * (1.0f / NSRC));
    return;
  }

  // ---- n > SCAP: exact chunked two-pass recompute (never expected) ----
  const int warp = t >> 5, lane = t & 31;
  __shared__ __align__(16) float qsh[2 * HID];
  __shared__ float2 ecache2[SCAP];
  __shared__ int s_warp4[4];
  __shared__ float zr[8];
  __shared__ float sZ0, sZ1;

  qsh[t] = q[((size_t)m << 8) + t];
  qsh[t + 128] = q[((size_t)m << 8) + t + 128];

  const float4* brow4 = (const float4*)(bias + (size_t)m * NSRC);

  // helper lambda: compact chunk [c0, c0+SCAP) into ish, return count
  auto compact = [&](int c0) -> int {
    float4 v0 = brow4[c0 / 4 + t * 2];
    float4 v1 = brow4[c0 / 4 + t * 2 + 1];
    int ccnt = (v0.x>0.f)+(v0.y>0.f)+(v0.z>0.f)+(v0.w>0.f)
             + (v1.x>0.f)+(v1.y>0.f)+(v1.z>0.f)+(v1.w>0.f);
    int cinc = ccnt;
    #pragma unroll
    for (int o = 1; o < 32; o <<= 1) {
      int u = __shfl_up_sync(0xffffffffu, cinc, o);
      if (lane >= o) cinc += u;
    }
    if (lane == 31) s_warp4[warp] = cinc;
    __syncthreads();
    int cn = 0, cwoff = 0;
    #pragma unroll
    for (int i = 0; i < 4; i++) {
      int u = s_warp4[i];
      cn += u;
      if (i < warp) cwoff += u;
    }
    int base = cwoff + cinc - ccnt;
    int b0 = c0 + t * 8;
    if (v0.x > 0.f) ish[base++] = (unsigned short)(b0 + 0);
    if (v0.y > 0.f) ish[base++] = (unsigned short)(b0 + 1);
    if (v0.z > 0.f) ish[base++] = (unsigned short)(b0 + 2);
    if (v0.w > 0.f) ish[base++] = (unsigned short)(b0 + 3);
    if (v1.x > 0.f) ish[base++] = (unsigned short)(b0 + 4);
    if (v1.y > 0.f) ish[base++] = (unsigned short)(b0 + 5);
    if (v1.z > 0.f) ish[base++] = (unsigned short)(b0 + 6);
    if (v1.w > 0.f) ish[base++] = (unsigned short)(b0 + 7);
    __syncthreads();
    return cn;
  };

  // pass 1: Z only
  float zp0 = 0.f, zp1 = 0.f;
  for (int c0 = 0; c0 < NSRC; c0 += SCAP) {
    __syncthreads();
    int cn = compact(c0);
    for (int j = t; j < cn; j += 128) {
      float2 e = score_exp_thread(ish[j], qsh, hsrc);
      zp0 += e.x; zp1 += e.y;
    }
  }
  // block-reduce zp
  #pragma unroll
  for (int o = 16; o; o >>= 1) {
    zp0 += __shfl_xor_sync(0xffffffffu, zp0, o);
    zp1 += __shfl_xor_sync(0xffffffffu, zp1, o);
  }
  if (lane == 0) { zr[warp] = zp0; zr[4 + warp] = zp1; }
  __syncthreads();
  if (t == 0) {
    float z0 = 0.f, z1 = 0.f;
    #pragma unroll
    for (int i = 0; i < 4; i++) { z0 += zr[i]; z1 += zr[4 + i]; }
    sZ0 = z0; sZ1 = z1;
  }
  __syncthreads();
  const float inv0 = 0.5f / sZ0;
  const float inv1 = 0.5f / sZ1;

  // pass 2: normalized gather
  float fx = 0.f, fy = 0.f;
  for (int c0 = 0; c0 < NSRC; c0 += SCAP) {
    __syncthreads();
    int cn = compact(c0);
    for (int j = warp; j < cn; j += 4) {
      float2 e = score_exp_pair(ish[j], qsh, hsrc, lane);
      if (lane == 0) ecache2[j] = e;
    }
    __syncthreads();
    for (int j = 0; j < cn; j++) {
      float2 e = ecache2[j];
      float wv = e.x * inv0 + e.y * inv1;
      float2 x = __half22float2(*(const __half2*)(xh + ish[j] * TFD + 2*t));
      fx += wv * x.x; fy += wv * x.y;
    }
  }
  *(float2*)(out + (size_t)m * TFD + 2*t) = make_float2(fx, fy);
}

// ---------------------------------------------------------------------------
extern "C" void kernel_launch(void* const* d_in, const int* in_sizes, int n_in,
                              void* d_out, int out_size)
{
  const float* bias        = (const float*)d_in[0];
  const float* emb_dest    = (const float*)d_in[1];
  const float* emb_src     = (const float*)d_in[2];
  const float* feature_src = (const float*)d_in[3];
  const float* fc_W        = (const float*)d_in[4];
  const float* fc_b        = (const float*)d_in[5];
  const float* dec_W       = (const float*)d_in[6];
  const float* dec_b       = (const float*)d_in[7];
  const float* att_W       = (const float*)d_in[8];
  const float* att_W2      = (const float*)d_in[9];

  float* out_re  = (float*)d_out;
  float* out_hat = out_re + (size_t)NDEST * TFD;

  __half *fcW_h, *decW_h, *trans_h, *hsrc_h;
  float *qp, *wc, *wcsr;
  unsigned short* icsr;
  int* ccsr;
  cudaGetSymbolAddress((void**)&fcW_h, g_fcW_h);
  cudaGetSymbolAddress((void**)&decW_h, g_decW_h);
  cudaGetSymbolAddress((void**)&trans_h, g_trans_h);
  cudaGetSymbolAddress((void**)&hsrc_h, g_hsrc_h);
  cudaGetSymbolAddress((void**)&qp, g_q);
  cudaGetSymbolAddress((void**)&wc, g_wc);
  cudaGetSymbolAddress((void**)&wcsr, g_w);
  cudaGetSymbolAddress((void**)&icsr, g_idx);
  cudaGetSymbolAddress((void**)&ccsr, g_cnt);

  cudaFuncSetAttribute(h16gemm_k<true, true>,
                       cudaFuncAttributeMaxDynamicSharedMemorySize, GSM_BYTES);
  cudaFuncSetAttribute(h16gemm_k<false, false>,
                       cudaFuncAttributeMaxDynamicSharedMemorySize, GSM_BYTES);

  // small weight conversions to fp16
  f2h_kernel<<<(TFD*FEATD/4 + 255)/256, 256>>>(fc_W, fcW_h, TFD*FEATD);
  f2h_kernel<<<(FEATD*TFD/4 + 255)/256, 256>>>(dec_W, decW_h, FEATD*TFD);

  // Wc[h] = att_W[h] @ att_W2[h]
  wc_kernel<<<128, 128>>>(att_W, att_W2, wc);

  // hsrc (fp16 interleaved) + q (fp32 interleaved) in one batched launch
  sgemm4_k<<<dim3(HID / 64, NSRC / 64, 4), 256>>>(
      emb_src, emb_dest, att_W, wc, hsrc_h, qp);

  // scores -> CSR
  score_kernel<<<NDEST, 256>>>(bias, qp, hsrc_h, wcsr, icsr, ccsr);

  // transformed = feature_src @ fc_W^T + fc_b (fp32 A converted in-kernel)
  h16gemm_k<true, true><<<dim3(TFD / 64, NSRC / 128), 256, GSM_BYTES>>>(
      feature_src, fcW_h, fc_b, trans_h, NSRC, TFD, FEATD);

  // feature_hat = transformed @ dec_W^T + dec_b
  h16gemm_k<false, false><<<dim3(FEATD / 64, NSRC / 128), 256, GSM_BYTES>>>(
      trans_h, decW_h, dec_b, out_hat, NSRC, FEATD, TFD);

  // CSR gather
  gather_kernel<<<NDEST, 128>>>(wcsr, icsr, ccsr, trans_h,
                                bias, qp, hsrc_h, out_re);
}